// round 14
// baseline (speedup 1.0000x reference)
#include <cuda_runtime.h>
#include <cstddef>

// Problem constants (fixed by the dataset instance)
#define MM   4
#define AA   256
#define RBF  64
#define FF   32
#define HH   32
#define SI   32
#define CC   128   // 4 filters * FF radial columns

// Precombined radial weights, row-major over k: g_Wt[k*CC + c]
__device__ float g_Wt[RBF * CC];
__device__ float g_bias[CC];
// feat1 transposed to component-major planes: g_f1t[m][d][b][f]
__device__ float g_f1t[MM * 3 * AA * FF];
// per-(half, ma) partial cat features: [2][1024][352]
__device__ float g_part[2 * MM * AA * 352];

struct Wptrs {
    const float* w1[4];
    const float* b1[4];
    const float* w2[4];
    const float* b2[4];
};

// ---------------------------------------------------------------------------
// Merged prep: feat1 transpose + W = w1@w2 (+ bias) in one launch.
// ---------------------------------------------------------------------------
#define N_F1T (MM * 3 * AA * FF)   // 98304
__global__ void prep_all(Wptrs wp, const float* __restrict__ feat1) {
    int idx = blockIdx.x * blockDim.x + threadIdx.x;
    if (idx < N_F1T) {
        int f = idx & 31;
        int b = (idx >> 5) & 255;
        int d = (idx >> 13) % 3;
        int m = idx / (3 * AA * FF);
        g_f1t[idx] = feat1[(((size_t)m * AA + b) * FF + f) * 3 + d];
    } else if (idx < N_F1T + CC * RBF) {
        int j = idx - N_F1T;
        int c = j & (CC - 1);
        int k = j >> 7;
        int filt = c >> 5;
        int f = c & 31;
        const float* w1 = wp.w1[filt];
        const float* w2 = wp.w2[filt];
        float s = 0.f;
#pragma unroll
        for (int h = 0; h < HH; h++)
            s += w1[k * HH + h] * w2[h * FF + f];
        g_Wt[k * CC + c] = s;
        if (k == 0) {
            float bs = wp.b2[filt][f];
            const float* b1 = wp.b1[filt];
#pragma unroll
            for (int h = 0; h < HH; h++)
                bs += b1[h] * w2[h * FF + f];
            g_bias[c] = bs;
        }
    }
}

// ---------------------------------------------------------------------------
// Packed fp32x2 helpers (Blackwell FFMA2 — PTX-only path)
// ---------------------------------------------------------------------------
typedef unsigned long long u64;

__device__ __forceinline__ u64 ffma2(u64 a, u64 b, u64 c) {
    u64 d;
    asm("fma.rn.f32x2 %0, %1, %2, %3;" : "=l"(d) : "l"(a), "l"(b), "l"(c));
    return d;
}
__device__ __forceinline__ u64 splat2(float x) {
    u64 d;
    asm("mov.b64 %0, {%1, %1};" : "=l"(d) : "f"(x));
    return d;
}
__device__ __forceinline__ float2 unpk(u64 a) {
    float2 r;
    asm("mov.b64 {%0, %1}, %2;" : "=f"(r.x), "=f"(r.y) : "l"(a));
    return r;
}
__device__ __forceinline__ float sspf(float x) {
    return logf(0.5f * expf(x) + 0.5f);   // shifted softplus
}

// smem floats: R(128*128, aliases Ism 64*128) + v(128*4) + red(8*32*12)
#define SMEM_FLOATS (128 * 128 + 128 * 4 + 8 * 32 * 12)

// ---------------------------------------------------------------------------
// Main fused kernel: one block per (m, a, half).  256 threads, 2 CTAs/SM.
// Each block handles 128 neighbor rows (b = half*128 .. +127).
// Phase A (GEMM): tc=tid>>4 owns c=8tc..8tc+7; tb=tid&15 owns
//   b in {4tb..4tb+3} U {64+4tb..+3}  -> conflict-free LDS.128.
//   k-loop is explicitly software-pipelined (prefetch k+1 img/W).
// Radial tile R[128b][128c] in smem with XOR swizzle (cq ^= (b>>2)&7).
// Phase B (contraction): warp w owns 16 b-rows, lane = f -> coalesced feats.
// Partials (32 f x 11 cols) written to g_part; finish kernel does SI.
// ---------------------------------------------------------------------------
__global__ void __launch_bounds__(256, 2) conv_kernel(
    const float* __restrict__ image,
    const float* __restrict__ vectors,
    const float* __restrict__ feat0)
{
    extern __shared__ float sm[];
    float* s_R   = sm;                       // [128][128] swizzled (64 KB)
    float* Ism   = sm;                       // [64][128] aliases R (dead pre-R)
    float* s_v   = sm + 128 * 128;           // [128][4] (this half's vectors)
    float* s_red = s_v + 128 * 4;            // [8][32][12]

    const int bid  = blockIdx.x;
    const int ma   = bid >> 1;               // m*AA + a
    const int half = bid & 1;
    const int m    = ma >> 8;
    const int tid  = threadIdx.x;
    const int tc   = tid >> 4;               // 0..15 (GEMM c-group)
    const int tb   = tid & 15;               // 0..15 (GEMM b-group)
    const int c0   = tc * 8;
    const int w    = tid >> 5;               // warp 0..7
    const int lane = tid & 31;               // = f in phase B

    const float* imgbase = image   + (size_t)ma * (AA * RBF);
    const float* vbase   = vectors + (size_t)ma * (AA * 3);
    const float* f0base  = feat0   + (size_t)m  * (AA * FF);
    const float* f1t0 = g_f1t + (size_t)(m * 3 + 0) * (AA * FF);
    const float* f1t1 = g_f1t + (size_t)(m * 3 + 1) * (AA * FF);
    const float* f1t2 = g_f1t + (size_t)(m * 3 + 2) * (AA * FF);

    // this half's 128 neighbor vectors (padded to 4)
    for (int u = tid; u < 384; u += 256)
        s_v[(u / 3) * 4 + (u % 3)] = vbase[half * 384 + u];

    float bias[8];
    {
        float4 ba = *(const float4*)(g_bias + c0);
        float4 bb = *(const float4*)(g_bias + c0 + 4);
        bias[0] = ba.x; bias[1] = ba.y; bias[2] = ba.z; bias[3] = ba.w;
        bias[4] = bb.x; bias[5] = bb.y; bias[6] = bb.z; bias[7] = bb.w;
    }

    // ---- stage 128 rows x 64 k, transposed into Ism[k][b] ----
    {
        const int sb  = tid & 127;           // b row within half
        const int skq = tid >> 7;            // 32-k half
        const float4* src = (const float4*)(imgbase +
            (size_t)(half * 128 + sb) * RBF + skq * 32);
#pragma unroll
        for (int j = 0; j < 8; j++) {
            float4 v = __ldg(src + j);
            const int k0 = skq * 32 + j * 4;
            Ism[(k0 + 0) * 128 + sb] = v.x;
            Ism[(k0 + 1) * 128 + sb] = v.y;
            Ism[(k0 + 2) * 128 + sb] = v.z;
            Ism[(k0 + 3) * 128 + sb] = v.w;
        }
    }
    __syncthreads();

    // ---- 8b x 8c register-tiled GEMM over k=64 (pipelined, conflict-free) --
    u64 t[8][4];
#pragma unroll
    for (int ci = 0; ci < 8; ci++)
#pragma unroll
        for (int bp = 0; bp < 4; bp++) t[ci][bp] = 0ULL;

    {
        const float4* wrow = (const float4*)(g_Wt + c0);
        u64 ni0, ni1, ni2, ni3;
        float4 nwa, nwb;
        {
            const u64* pA = (const u64*)(Ism + tb * 4);
            const u64* pB = (const u64*)(Ism + 64 + tb * 4);
            ni0 = pA[0]; ni1 = pA[1]; ni2 = pB[0]; ni3 = pB[1];
            nwa = __ldg(wrow); nwb = __ldg(wrow + 1);
        }
#pragma unroll 8
        for (int k = 0; k < 64; k++) {
            u64 i0 = ni0, i1 = ni1, i2 = ni2, i3 = ni3;
            float4 wa = nwa, wb = nwb;
            if (k + 1 < 64) {
                const u64* pA = (const u64*)(Ism + (k + 1) * 128 + tb * 4);
                const u64* pB = (const u64*)(Ism + (k + 1) * 128 + 64 + tb * 4);
                ni0 = pA[0]; ni1 = pA[1]; ni2 = pB[0]; ni3 = pB[1];
                nwa = __ldg(wrow + (k + 1) * 32);
                nwb = __ldg(wrow + (k + 1) * 32 + 1);
            }
            u64 ww;
            ww = splat2(wa.x);
            t[0][0]=ffma2(i0,ww,t[0][0]); t[0][1]=ffma2(i1,ww,t[0][1]);
            t[0][2]=ffma2(i2,ww,t[0][2]); t[0][3]=ffma2(i3,ww,t[0][3]);
            ww = splat2(wa.y);
            t[1][0]=ffma2(i0,ww,t[1][0]); t[1][1]=ffma2(i1,ww,t[1][1]);
            t[1][2]=ffma2(i2,ww,t[1][2]); t[1][3]=ffma2(i3,ww,t[1][3]);
            ww = splat2(wa.z);
            t[2][0]=ffma2(i0,ww,t[2][0]); t[2][1]=ffma2(i1,ww,t[2][1]);
            t[2][2]=ffma2(i2,ww,t[2][2]); t[2][3]=ffma2(i3,ww,t[2][3]);
            ww = splat2(wa.w);
            t[3][0]=ffma2(i0,ww,t[3][0]); t[3][1]=ffma2(i1,ww,t[3][1]);
            t[3][2]=ffma2(i2,ww,t[3][2]); t[3][3]=ffma2(i3,ww,t[3][3]);
            ww = splat2(wb.x);
            t[4][0]=ffma2(i0,ww,t[4][0]); t[4][1]=ffma2(i1,ww,t[4][1]);
            t[4][2]=ffma2(i2,ww,t[4][2]); t[4][3]=ffma2(i3,ww,t[4][3]);
            ww = splat2(wb.y);
            t[5][0]=ffma2(i0,ww,t[5][0]); t[5][1]=ffma2(i1,ww,t[5][1]);
            t[5][2]=ffma2(i2,ww,t[5][2]); t[5][3]=ffma2(i3,ww,t[5][3]);
            ww = splat2(wb.z);
            t[6][0]=ffma2(i0,ww,t[6][0]); t[6][1]=ffma2(i1,ww,t[6][1]);
            t[6][2]=ffma2(i2,ww,t[6][2]); t[6][3]=ffma2(i3,ww,t[6][3]);
            ww = splat2(wb.w);
            t[7][0]=ffma2(i0,ww,t[7][0]); t[7][1]=ffma2(i1,ww,t[7][1]);
            t[7][2]=ffma2(i2,ww,t[7][2]); t[7][3]=ffma2(i3,ww,t[7][3]);
        }
    }
    __syncthreads();   // Ism dead; safe to clobber with R

    // ---- write radial tile R[b][c] (swizzled, conflict-free STS.128) ----
#pragma unroll
    for (int bp = 0; bp < 4; bp++) {
        const int bBase = tb * 4 + ((bp >> 1) << 6) + (bp & 1) * 2;
#pragma unroll
        for (int h = 0; h < 2; h++) {
            const int b = bBase + h;
            const int xw = (b >> 2) & 7;
            float4 lo, hi;
            {
                float2 u0 = unpk(t[0][bp]), u1 = unpk(t[1][bp]);
                float2 u2 = unpk(t[2][bp]), u3 = unpk(t[3][bp]);
                lo.x = (h ? u0.y : u0.x) + bias[0];
                lo.y = (h ? u1.y : u1.x) + bias[1];
                lo.z = (h ? u2.y : u2.x) + bias[2];
                lo.w = (h ? u3.y : u3.x) + bias[3];
                float2 u4 = unpk(t[4][bp]), u5 = unpk(t[5][bp]);
                float2 u6 = unpk(t[6][bp]), u7 = unpk(t[7][bp]);
                hi.x = (h ? u4.y : u4.x) + bias[4];
                hi.y = (h ? u5.y : u5.x) + bias[5];
                hi.z = (h ? u6.y : u6.x) + bias[6];
                hi.w = (h ? u7.y : u7.x) + bias[7];
            }
            const int cqLo = (tc * 2) ^ xw;
            const int cqHi = (tc * 2 + 1) ^ xw;
            *(float4*)(s_R + b * 128 + cqLo * 4) = lo;
            *(float4*)(s_R + b * 128 + cqHi * 4) = hi;
        }
    }
    __syncthreads();

    // ---- contraction: warp w owns 16 b-rows; lane = f ----
    float a[11];
#pragma unroll
    for (int j = 0; j < 11; j++) a[j] = 0.f;

#pragma unroll 4
    for (int i = 0; i < 16; i++) {
        const int bl = w * 16 + i;            // row in R (local b)
        const int b  = half * 128 + bl;       // global neighbor
        const float p0 = __ldg(f0base + b * FF + lane);
        const float q0 = __ldg(f1t0 + b * FF + lane);
        const float q1 = __ldg(f1t1 + b * FF + lane);
        const float q2 = __ldg(f1t2 + b * FF + lane);
        const float vx = s_v[bl * 4], vy = s_v[bl * 4 + 1], vz = s_v[bl * 4 + 2];
        const int xw  = (bl >> 2) & 7;
        const int off = (((lane >> 2) ^ xw) << 2) + (lane & 3);
        const float* rp = s_R + bl * 128 + off;
        const float r00 = rp[0];
        const float r01 = rp[32];
        const float r10 = rp[64];
        const float r11 = rp[96];
        const float n2 = vx * vx + vy * vy + vz * vz;
        const float mk = (n2 < 1e-14f) ? 0.f : 1.f;

        a[0] += r00 * p0;                        // out_0x0_0
        const float t1 = r01 * mk * p0;          // out_0x1_1
        a[1] += t1 * vx;  a[2] += t1 * vy;  a[3] += t1 * vz;
        a[4] += r10 * q0; a[5] += r10 * q1; a[6] += r10 * q2;  // out_1x0_1
        const float rm = r11 * mk;               // out_1x1_0 / _1
        a[7]  += rm * (vx * q0 + vy * q1 + vz * q2);
        a[8]  += rm * (vy * q2 - vz * q1);
        a[9]  += rm * (vz * q0 - vx * q2);
        a[10] += rm * (vx * q1 - vy * q0);
    }

    // ---- cross-warp reduction -> global partials ----
#pragma unroll
    for (int j = 0; j < 11; j++) s_red[(w * 32 + lane) * 12 + j] = a[j];
    __syncthreads();

    float* part = g_part + (size_t)(half * (MM * AA) + ma) * 352;
    for (int idx = tid; idx < 352; idx += 256) {
        const int f = idx / 11, col = idx % 11;
        float s = 0.f;
#pragma unroll
        for (int g = 0; g < 8; g++)
            s += s_red[(g * 32 + f) * 12 + col];
        part[idx] = s;
    }
}

// ---------------------------------------------------------------------------
// Finish: combine halves, self-interaction, equivariant activation.
// One block per (m, a), 64 threads.
// ---------------------------------------------------------------------------
__global__ void __launch_bounds__(64) finish_kernel(
    const float* __restrict__ w_si0,
    const float* __restrict__ w_si1,
    const float* __restrict__ b_act0,
    const float* __restrict__ b_act1,
    float* __restrict__ out)
{
    __shared__ float s_cat[352];
    const int ma  = blockIdx.x;
    const int tid = threadIdx.x;

    const float* p0 = g_part + (size_t)ma * 352;
    const float* p1 = g_part + (size_t)(MM * AA + ma) * 352;
    for (int idx = tid; idx < 352; idx += 64)
        s_cat[idx] = p0[idx] + p1[idx];
    __syncthreads();

    if (tid < 32) {
        const int g = tid;
        const float* w0p = w_si0 + g * (2 * FF);
        const float* w1p = w_si1 + g * (3 * FF);
        float si0 = 0.f, sx = 0.f, sy = 0.f, sz = 0.f;
#pragma unroll 8
        for (int f2 = 0; f2 < 32; f2++) {
            const float* c = s_cat + f2 * 11;
            si0 += w0p[f2] * c[0] + w0p[32 + f2] * c[7];
            const float wa = w1p[f2], wb = w1p[32 + f2], wc = w1p[64 + f2];
            sx += wa * c[1] + wb * c[4] + wc * c[8];
            sy += wa * c[2] + wb * c[5] + wc * c[9];
            sz += wa * c[3] + wb * c[6] + wc * c[10];
        }
        const float o0v = sspf(si0 + b_act0[g]);
        const float nn  = sx * sx + sy * sy + sz * sz;
        const float n1  = sqrtf(fmaxf(nn, 1e-7f));
        const float a1v = sspf(n1 + b_act1[g]);
        const float sc  = a1v / n1;

        out[(size_t)ma * SI + g] = o0v;                      // o0: (M,A,SI,1)
        float* o1 = out + (size_t)MM * AA * SI + ((size_t)ma * SI + g) * 3;
        o1[0] = sx * sc;
        o1[1] = sy * sc;
        o1[2] = sz * sc;
    }
}

// ---------------------------------------------------------------------------
extern "C" void kernel_launch(void* const* d_in, const int* in_sizes, int n_in,
                              void* d_out, int out_size)
{
    (void)in_sizes; (void)n_in; (void)out_size;

    const float* image   = (const float*)d_in[0];
    const float* vectors = (const float*)d_in[1];
    const float* feat0   = (const float*)d_in[2];
    const float* feat1   = (const float*)d_in[3];

    Wptrs wp;
    for (int filt = 0; filt < 4; filt++) {
        wp.w1[filt] = (const float*)d_in[4 + filt * 4 + 0];
        wp.b1[filt] = (const float*)d_in[4 + filt * 4 + 1];
        wp.w2[filt] = (const float*)d_in[4 + filt * 4 + 2];
        wp.b2[filt] = (const float*)d_in[4 + filt * 4 + 3];
    }
    const float* w_si0  = (const float*)d_in[20];
    const float* w_si1  = (const float*)d_in[21];
    const float* b_act0 = (const float*)d_in[22];
    const float* b_act1 = (const float*)d_in[23];

    const int smem_bytes = SMEM_FLOATS * (int)sizeof(float);
    cudaFuncSetAttribute(conv_kernel,
                         cudaFuncAttributeMaxDynamicSharedMemorySize,
                         smem_bytes);

    const int prep_total = N_F1T + CC * RBF;
    prep_all<<<(prep_total + 255) / 256, 256>>>(wp, feat1);
    conv_kernel<<<MM * AA * 2, 256, smem_bytes>>>(image, vectors, feat0);
    finish_kernel<<<MM * AA, 64>>>(w_si0, w_si1, b_act0, b_act1,
                                   (float*)d_out);
}

// round 15
// speedup vs baseline: 1.1355x; 1.1355x over previous
#include <cuda_runtime.h>
#include <cstddef>

// Problem constants (fixed by the dataset instance)
#define MM   4
#define AA   256
#define RBF  64
#define FF   32
#define HH   32
#define SI   32
#define CC   128   // 4 filters * FF radial columns

// Precombined radial weights, row-major over k: g_Wt[k*CC + c]
__device__ float g_Wt[RBF * CC];
__device__ float g_bias[CC];
// feat1 transposed to component-major planes: g_f1t[m][d][b][f]
__device__ float g_f1t[MM * 3 * AA * FF];
// per-(half, ma) partial cat features: [2][1024][352]
__device__ float g_part[2 * MM * AA * 352];

struct Wptrs {
    const float* w1[4];
    const float* b1[4];
    const float* w2[4];
    const float* b2[4];
};

// ---------------------------------------------------------------------------
// Merged prep: feat1 transpose + W = w1@w2 (+ bias) in one launch.
// ---------------------------------------------------------------------------
#define N_F1T (MM * 3 * AA * FF)   // 98304
__global__ void prep_all(Wptrs wp, const float* __restrict__ feat1) {
    int idx = blockIdx.x * blockDim.x + threadIdx.x;
    if (idx < N_F1T) {
        int f = idx & 31;
        int b = (idx >> 5) & 255;
        int d = (idx >> 13) % 3;
        int m = idx / (3 * AA * FF);
        g_f1t[idx] = feat1[(((size_t)m * AA + b) * FF + f) * 3 + d];
    } else if (idx < N_F1T + CC * RBF) {
        int j = idx - N_F1T;
        int c = j & (CC - 1);
        int k = j >> 7;
        int filt = c >> 5;
        int f = c & 31;
        const float* w1 = wp.w1[filt];
        const float* w2 = wp.w2[filt];
        float s = 0.f;
#pragma unroll
        for (int h = 0; h < HH; h++)
            s += w1[k * HH + h] * w2[h * FF + f];
        g_Wt[k * CC + c] = s;
        if (k == 0) {
            float bs = wp.b2[filt][f];
            const float* b1 = wp.b1[filt];
#pragma unroll
            for (int h = 0; h < HH; h++)
                bs += b1[h] * w2[h * FF + f];
            g_bias[c] = bs;
        }
    }
}

// ---------------------------------------------------------------------------
// Packed fp32x2 helpers (Blackwell FFMA2 — PTX-only path)
// ---------------------------------------------------------------------------
typedef unsigned long long u64;

__device__ __forceinline__ u64 ffma2(u64 a, u64 b, u64 c) {
    u64 d;
    asm("fma.rn.f32x2 %0, %1, %2, %3;" : "=l"(d) : "l"(a), "l"(b), "l"(c));
    return d;
}
__device__ __forceinline__ u64 splat2(float x) {
    u64 d;
    asm("mov.b64 %0, {%1, %1};" : "=l"(d) : "f"(x));
    return d;
}
__device__ __forceinline__ float2 unpk(u64 a) {
    float2 r;
    asm("mov.b64 {%0, %1}, %2;" : "=f"(r.x), "=f"(r.y) : "l"(a));
    return r;
}
__device__ __forceinline__ float sspf(float x) {
    return logf(0.5f * expf(x) + 0.5f);   // shifted softplus
}

// smem floats: R(128*128, aliases Ism 64*128) + v(128*4) + red(4*32*11)
#define SMEM_FLOATS (128 * 128 + 128 * 4 + 4 * 32 * 11)

// ---------------------------------------------------------------------------
// Main fused kernel: one block per (m, a, half).  128 threads, 2 CTAs/SM.
// Each block handles 128 neighbor rows (b = half*128 .. +127).
//
// GEMM geometry: thread (tc, tb) owns 8 c (c0=8tc) x 16 b (chunks tb, tb+8,
//   tb+16, tb+24).  Warp = 4 tb-groups x 8 tc-groups:
//     - image chunk read by 8 lanes -> broadcast dedup, 4 wf/k/warp
//     - W via LDG, 256B/k/warp (L1-resident)
// Ism swizzle: (k,b) at k*128 + ((bq ^ ((k>>2)&7))<<2) + (b&3) — conflict-
//   free GEMM LDS.128, 2-way staging STS.32, coalesced staging LDG.
// R swizzle: chunk cq=(c>>2) of row b at ch = ((cq>>1 + b)&15) | ((cq&1)<<4)
//   — 2-way STS.128 write, 2-way LDS.32 phase-B read.
// Phase B: warp w owns 32 b-rows, lane = f -> coalesced feat loads.
// ---------------------------------------------------------------------------
__global__ void __launch_bounds__(128, 2) conv_kernel(
    const float* __restrict__ image,
    const float* __restrict__ vectors,
    const float* __restrict__ feat0)
{
    extern __shared__ float sm[];
    float* s_R   = sm;                       // [128][128] swizzled (64 KB)
    float* Ism   = sm;                       // [64][128] aliases R (dead pre-R)
    float* s_v   = sm + 128 * 128;           // [128][4] (this half's vectors)
    float* s_red = s_v + 128 * 4;            // [4][32][11]

    const int bid  = blockIdx.x;
    const int ma   = bid >> 1;               // m*AA + a
    const int half = bid & 1;
    const int m    = ma >> 8;
    const int tid  = threadIdx.x;
    const int w    = tid >> 5;               // warp 0..3
    const int lane = tid & 31;               // = f in phase B
    const int tc   = (lane & 7) | ((w & 1) << 3);   // 0..15: 8 c each
    const int tb   = ((lane >> 3) & 3) | ((w >> 1) << 2); // 0..7: 16 b each
    const int c0   = tc * 8;

    const float* imgbase = image   + (size_t)ma * (AA * RBF);
    const float* vbase   = vectors + (size_t)ma * (AA * 3);
    const float* f0base  = feat0   + (size_t)m  * (AA * FF);
    const float* f1t0 = g_f1t + (size_t)(m * 3 + 0) * (AA * FF);
    const float* f1t1 = g_f1t + (size_t)(m * 3 + 1) * (AA * FF);
    const float* f1t2 = g_f1t + (size_t)(m * 3 + 2) * (AA * FF);

    // this half's 128 neighbor vectors (padded to 4)
    for (int u = tid; u < 384; u += 128)
        s_v[(u / 3) * 4 + (u % 3)] = vbase[half * 384 + u];

    float bias[8];
    {
        float4 ba = *(const float4*)(g_bias + c0);
        float4 bb = *(const float4*)(g_bias + c0 + 4);
        bias[0] = ba.x; bias[1] = ba.y; bias[2] = ba.z; bias[3] = ba.w;
        bias[4] = bb.x; bias[5] = bb.y; bias[6] = bb.z; bias[7] = bb.w;
    }

    // ---- stage 128 rows x 64 k (coalesced LDG, swizzled transpose STS) ----
#pragma unroll
    for (int j = 0; j < 16; j++) {
        const int idx = j * 128 + tid;       // float4 index in 128x16 tile
        const int b   = idx >> 4;
        const int kq  = idx & 15;
        float4 v = __ldg((const float4*)(imgbase +
                    (size_t)(half * 128 + b) * RBF) + kq);
        const int ch  = ((b >> 2) ^ (kq & 7)) << 2;
        float* dst = Ism + (kq * 4) * 128 + ch + (b & 3);
        dst[0]       = v.x;
        dst[128]     = v.y;
        dst[256]     = v.z;
        dst[384]     = v.w;
    }
    __syncthreads();

    // ---- 16b x 8c register-tiled GEMM over k=64 ----
    u64 t[8][8];
#pragma unroll
    for (int ci = 0; ci < 8; ci++)
#pragma unroll
        for (int bp = 0; bp < 8; bp++) t[ci][bp] = 0ULL;

#pragma unroll 4
    for (int g = 0; g < 16; g++) {
        const int xg  = g & 7;
        const int ch0 = ((tb ^ xg) << 2);    // chunk r: ch0 + 32r floats
#pragma unroll
        for (int c = 0; c < 4; c++) {
            const int k = g * 4 + c;
            const float* row = Ism + k * 128 + ch0;
            const u64* p0 = (const u64*)(row);
            const u64* p1 = (const u64*)(row + 32);
            const u64* p2 = (const u64*)(row + 64);
            const u64* p3 = (const u64*)(row + 96);
            u64 lo0 = p0[0], hi0 = p0[1];
            u64 lo1 = p1[0], hi1 = p1[1];
            u64 lo2 = p2[0], hi2 = p2[1];
            u64 lo3 = p3[0], hi3 = p3[1];
            float4 wa = __ldg((const float4*)(g_Wt + k * CC + c0));
            float4 wb = __ldg((const float4*)(g_Wt + k * CC + c0) + 1);
            float wreg[8] = {wa.x, wa.y, wa.z, wa.w, wb.x, wb.y, wb.z, wb.w};
#pragma unroll
            for (int ci = 0; ci < 8; ci++) {
                u64 ww = splat2(wreg[ci]);
                t[ci][0] = ffma2(lo0, ww, t[ci][0]);
                t[ci][1] = ffma2(hi0, ww, t[ci][1]);
                t[ci][2] = ffma2(lo1, ww, t[ci][2]);
                t[ci][3] = ffma2(hi1, ww, t[ci][3]);
                t[ci][4] = ffma2(lo2, ww, t[ci][4]);
                t[ci][5] = ffma2(hi2, ww, t[ci][5]);
                t[ci][6] = ffma2(lo3, ww, t[ci][6]);
                t[ci][7] = ffma2(hi3, ww, t[ci][7]);
            }
        }
    }
    __syncthreads();   // Ism dead; safe to clobber with R

    // ---- write radial tile R[b][c] (rotate-16 swizzle) ----
#pragma unroll
    for (int r = 0; r < 4; r++) {
#pragma unroll
        for (int p = 0; p < 2; p++) {
#pragma unroll
            for (int h = 0; h < 2; h++) {
                const int b = 4 * (tb + 8 * r) + 2 * p + h;
                float4 lo, hi;
                {
                    float2 u0 = unpk(t[0][2*r+p]), u1 = unpk(t[1][2*r+p]);
                    float2 u2 = unpk(t[2][2*r+p]), u3 = unpk(t[3][2*r+p]);
                    lo.x = (h ? u0.y : u0.x) + bias[0];
                    lo.y = (h ? u1.y : u1.x) + bias[1];
                    lo.z = (h ? u2.y : u2.x) + bias[2];
                    lo.w = (h ? u3.y : u3.x) + bias[3];
                    float2 u4 = unpk(t[4][2*r+p]), u5 = unpk(t[5][2*r+p]);
                    float2 u6 = unpk(t[6][2*r+p]), u7 = unpk(t[7][2*r+p]);
                    hi.x = (h ? u4.y : u4.x) + bias[4];
                    hi.y = (h ? u5.y : u5.x) + bias[5];
                    hi.z = (h ? u6.y : u6.x) + bias[6];
                    hi.w = (h ? u7.y : u7.x) + bias[7];
                }
                const int chLo = (tc + b) & 15;       // cq = 2tc   (c0..c0+3)
                const int chHi = chLo + 16;           // cq = 2tc+1 (c0+4..+7)
                *(float4*)(s_R + b * 128 + chLo * 4) = lo;
                *(float4*)(s_R + b * 128 + chHi * 4) = hi;
            }
        }
    }
    __syncthreads();

    // ---- contraction: warp w owns 32 b-rows; lane = f ----
    float a[11];
#pragma unroll
    for (int j = 0; j < 11; j++) a[j] = 0.f;

    const int f3   = lane >> 3;          // f>>3
    const int fhi  = ((lane >> 2) & 1) << 4;
    const int fpos = lane & 3;

#pragma unroll 4
    for (int i = 0; i < 32; i++) {
        const int bl = w * 32 + i;            // row in R (local b)
        const int b  = half * 128 + bl;       // global neighbor
        const float p0 = __ldg(f0base + b * FF + lane);
        const float q0 = __ldg(f1t0 + b * FF + lane);
        const float q1 = __ldg(f1t1 + b * FF + lane);
        const float q2 = __ldg(f1t2 + b * FF + lane);
        const float vx = s_v[bl * 4], vy = s_v[bl * 4 + 1], vz = s_v[bl * 4 + 2];
        const float* rrow = s_R + bl * 128;
        const float r00 = rrow[((((f3 +  0 + bl) & 15) | fhi) << 2) + fpos];
        const float r01 = rrow[((((f3 +  4 + bl) & 15) | fhi) << 2) + fpos];
        const float r10 = rrow[((((f3 +  8 + bl) & 15) | fhi) << 2) + fpos];
        const float r11 = rrow[((((f3 + 12 + bl) & 15) | fhi) << 2) + fpos];
        const float n2 = vx * vx + vy * vy + vz * vz;
        const float mk = (n2 < 1e-14f) ? 0.f : 1.f;

        a[0] += r00 * p0;                        // out_0x0_0
        const float t1 = r01 * mk * p0;          // out_0x1_1
        a[1] += t1 * vx;  a[2] += t1 * vy;  a[3] += t1 * vz;
        a[4] += r10 * q0; a[5] += r10 * q1; a[6] += r10 * q2;  // out_1x0_1
        const float rm = r11 * mk;               // out_1x1_0 / _1
        a[7]  += rm * (vx * q0 + vy * q1 + vz * q2);
        a[8]  += rm * (vy * q2 - vz * q1);
        a[9]  += rm * (vz * q0 - vx * q2);
        a[10] += rm * (vx * q1 - vy * q0);
    }

    // ---- cross-warp reduction -> global partials ----
#pragma unroll
    for (int j = 0; j < 11; j++) s_red[(w * 32 + lane) * 11 + j] = a[j];
    __syncthreads();

    float* part = g_part + (size_t)(half * (MM * AA) + ma) * 352;
    for (int idx = tid; idx < 352; idx += 128) {
        const int f = idx / 11, col = idx % 11;
        float s = 0.f;
#pragma unroll
        for (int g2 = 0; g2 < 4; g2++)
            s += s_red[(g2 * 32 + f) * 11 + col];
        part[idx] = s;
    }
}

// ---------------------------------------------------------------------------
// Finish: combine halves, self-interaction, equivariant activation.
// One block per (m, a), 64 threads.
// ---------------------------------------------------------------------------
__global__ void __launch_bounds__(64) finish_kernel(
    const float* __restrict__ w_si0,
    const float* __restrict__ w_si1,
    const float* __restrict__ b_act0,
    const float* __restrict__ b_act1,
    float* __restrict__ out)
{
    __shared__ float s_cat[352];
    const int ma  = blockIdx.x;
    const int tid = threadIdx.x;

    const float* p0 = g_part + (size_t)ma * 352;
    const float* p1 = g_part + (size_t)(MM * AA + ma) * 352;
    for (int idx = tid; idx < 352; idx += 64)
        s_cat[idx] = p0[idx] + p1[idx];
    __syncthreads();

    if (tid < 32) {
        const int g = tid;
        const float* w0p = w_si0 + g * (2 * FF);
        const float* w1p = w_si1 + g * (3 * FF);
        float si0 = 0.f, sx = 0.f, sy = 0.f, sz = 0.f;
#pragma unroll 8
        for (int f2 = 0; f2 < 32; f2++) {
            const float* c = s_cat + f2 * 11;
            si0 += w0p[f2] * c[0] + w0p[32 + f2] * c[7];
            const float wa = w1p[f2], wb = w1p[32 + f2], wc = w1p[64 + f2];
            sx += wa * c[1] + wb * c[4] + wc * c[8];
            sy += wa * c[2] + wb * c[5] + wc * c[9];
            sz += wa * c[3] + wb * c[6] + wc * c[10];
        }
        const float o0v = sspf(si0 + b_act0[g]);
        const float nn  = sx * sx + sy * sy + sz * sz;
        const float n1  = sqrtf(fmaxf(nn, 1e-7f));
        const float a1v = sspf(n1 + b_act1[g]);
        const float sc  = a1v / n1;

        out[(size_t)ma * SI + g] = o0v;                      // o0: (M,A,SI,1)
        float* o1 = out + (size_t)MM * AA * SI + ((size_t)ma * SI + g) * 3;
        o1[0] = sx * sc;
        o1[1] = sy * sc;
        o1[2] = sz * sc;
    }
}

// ---------------------------------------------------------------------------
extern "C" void kernel_launch(void* const* d_in, const int* in_sizes, int n_in,
                              void* d_out, int out_size)
{
    (void)in_sizes; (void)n_in; (void)out_size;

    const float* image   = (const float*)d_in[0];
    const float* vectors = (const float*)d_in[1];
    const float* feat0   = (const float*)d_in[2];
    const float* feat1   = (const float*)d_in[3];

    Wptrs wp;
    for (int filt = 0; filt < 4; filt++) {
        wp.w1[filt] = (const float*)d_in[4 + filt * 4 + 0];
        wp.b1[filt] = (const float*)d_in[4 + filt * 4 + 1];
        wp.w2[filt] = (const float*)d_in[4 + filt * 4 + 2];
        wp.b2[filt] = (const float*)d_in[4 + filt * 4 + 3];
    }
    const float* w_si0  = (const float*)d_in[20];
    const float* w_si1  = (const float*)d_in[21];
    const float* b_act0 = (const float*)d_in[22];
    const float* b_act1 = (const float*)d_in[23];

    const int smem_bytes = SMEM_FLOATS * (int)sizeof(float);
    cudaFuncSetAttribute(conv_kernel,
                         cudaFuncAttributeMaxDynamicSharedMemorySize,
                         smem_bytes);

    const int prep_total = N_F1T + CC * RBF;
    prep_all<<<(prep_total + 255) / 256, 256>>>(wp, feat1);
    conv_kernel<<<MM * AA * 2, 128, smem_bytes>>>(image, vectors, feat0);
    finish_kernel<<<MM * AA, 64>>>(w_si0, w_si1, b_act0, b_act1,
                                   (float*)d_out);
}

// round 17
// speedup vs baseline: 1.2320x; 1.0850x over previous
#include <cuda_runtime.h>
#include <cstddef>
#include <cstdint>

// Problem constants (fixed by the dataset instance)
#define MM   4
#define AA   256
#define RBF  64
#define FF   32
#define HH   32
#define SI   32
#define CC   128   // 4 filters * FF radial columns

// W packed in mma A-fragment order: [w(8)][kt(8)][lane(32)][reg(4)]
__device__ float g_WfH[8 * 8 * 32 * 4];
__device__ float g_WfL[8 * 8 * 32 * 4];
__device__ float g_bias[CC];
// feat1 transposed to component-major planes: g_f1t[m][d][b][f]
__device__ float g_f1t[MM * 3 * AA * FF];
// per-(half, ma) partial cat features: [2][1024][352]
__device__ float g_part[2 * MM * AA * 352];

struct Wptrs {
    const float* w1[4];
    const float* b1[4];
    const float* w2[4];
    const float* b2[4];
};

__device__ __forceinline__ float tf32_rna(float x) {
    uint32_t r;
    asm("cvt.rna.tf32.f32 %0, %1;" : "=r"(r) : "f"(x));
    return __uint_as_float(r);
}
__device__ __forceinline__ float sspf(float x) {
    return logf(0.5f * expf(x) + 0.5f);   // shifted softplus
}

// ---------------------------------------------------------------------------
// Prep: (a) feat1 transpose (float4 both ways), (b) W = w1@w2 split into
// tf32 hi/lo packed in A-frag order, (c) bias.
// ---------------------------------------------------------------------------
#define N_F1Q (MM * AA * FF / 4)     // 8192 f-quads
#define N_WFR (8 * 8 * 32)           // 2048 frag-threads
__global__ void prep_all(Wptrs wp, const float* __restrict__ feat1) {
    const int idx = blockIdx.x * blockDim.x + threadIdx.x;
    if (idx < N_F1Q) {
        // thread handles 4 f at one (m,b): 12 consecutive floats in feat1
        const int qf = idx & 7;
        const int b  = (idx >> 3) & 255;
        const int m  = idx >> 11;
        const float4* src = (const float4*)(feat1 +
            ((size_t)(m * AA + b) * FF + qf * 4) * 3);
        float4 u = src[0], v = src[1], w4 = src[2];
        float4 d0 = make_float4(u.x, u.w, v.z, w4.y);
        float4 d1 = make_float4(u.y, v.x, v.w, w4.z);
        float4 d2 = make_float4(u.z, v.y, w4.x, w4.w);
        const size_t o = (size_t)b * FF + qf * 4;
        *(float4*)(g_f1t + (size_t)(m * 3 + 0) * (AA * FF) + o) = d0;
        *(float4*)(g_f1t + (size_t)(m * 3 + 1) * (AA * FF) + o) = d1;
        *(float4*)(g_f1t + (size_t)(m * 3 + 2) * (AA * FF) + o) = d2;
    } else if (idx < N_F1Q + N_WFR) {
        const int t2   = idx - N_F1Q;           // (w*8+kt)*32 + lane
        const int lane = t2 & 31;
        const int ktw  = t2 >> 5;
        const int kt   = ktw & 7;
        const int w    = ktw >> 3;
        const int g    = lane >> 2;
        const int tg   = lane & 3;
#pragma unroll
        for (int j = 0; j < 4; j++) {
            const int c = 16 * w + g + 8 * (j & 1);
            const int k = 8 * kt + tg + 4 * (j >> 1);
            const int filt = c >> 5, f = c & 31;
            const float* w1 = wp.w1[filt];
            const float* w2 = wp.w2[filt];
            float s = 0.f;
#pragma unroll
            for (int h = 0; h < HH; h++)
                s += w1[k * HH + h] * w2[h * FF + f];
            const float hi = tf32_rna(s);
            g_WfH[t2 * 4 + j] = hi;
            g_WfL[t2 * 4 + j] = tf32_rna(s - hi);
        }
    } else if (idx < N_F1Q + N_WFR + CC) {
        const int c = idx - N_F1Q - N_WFR;
        const int filt = c >> 5, f = c & 31;
        float bs = wp.b2[filt][f];
        const float* b1 = wp.b1[filt];
        const float* w2 = wp.w2[filt];
#pragma unroll
        for (int h = 0; h < HH; h++)
            bs += b1[h] * w2[h * FF + f];
        g_bias[c] = bs;
    }
}

// ---------------------------------------------------------------------------
// smem layout (floats)
//   s_Ih [128][68]  image hi (tf32)      @ 0       (8704)
//   s_Il [128][68]  image lo (tf32)      @ 8704    (8704)
//   s_R  [128c][129] radial tile         @ 0       (16512, overlays Ih/Il)
//   s_v  [128][4]                        @ 17408   (512)
//   s_red[8][32][11]                     @ 17920   (2816)
// ---------------------------------------------------------------------------
#define PITCH_I 68
#define PITCH_R 129
#define SM_IL   8704
#define SM_V    17408
#define SM_RED  17920
#define SMEM_FLOATS 20736

__device__ __forceinline__ void mma_tf32(float* d, const uint4& a,
                                         uint32_t b0, uint32_t b1) {
    asm volatile(
        "mma.sync.aligned.m16n8k8.row.col.f32.tf32.tf32.f32 "
        "{%0,%1,%2,%3}, {%4,%5,%6,%7}, {%8,%9}, {%0,%1,%2,%3};"
        : "+f"(d[0]), "+f"(d[1]), "+f"(d[2]), "+f"(d[3])
        : "r"(a.x), "r"(a.y), "r"(a.z), "r"(a.w), "r"(b0), "r"(b1));
}

// ---------------------------------------------------------------------------
// Main kernel: one block per (m, a, half).  256 threads (8 warps), 2 CTAs/SM.
// GEMM: D[128c][128b] = W[128c x 64k] * I[64k x 128b] via mma.sync tf32
//   (3xTF32 split).  Warp w owns c rows [16w,16w+16); A-frags (W) prepacked
//   in global, B-frags (image) from pitch-68 smem (conflict-free).
// Phase B: warp w owns 16 b-rows, lane = f; R[c][129] reads conflict-free.
// ---------------------------------------------------------------------------
__global__ void __launch_bounds__(256, 2) conv_kernel(
    const float* __restrict__ image,
    const float* __restrict__ vectors,
    const float* __restrict__ feat0)
{
    extern __shared__ float sm[];
    float* s_Ih  = sm;
    float* s_Il  = sm + SM_IL;
    float* s_R   = sm;                   // overlays Ih/Il after GEMM
    float* s_v   = sm + SM_V;
    float* s_red = sm + SM_RED;

    const int bid  = blockIdx.x;
    const int ma   = bid >> 1;           // m*AA + a
    const int half = bid & 1;
    const int m    = ma >> 8;
    const int tid  = threadIdx.x;
    const int w    = tid >> 5;           // warp 0..7
    const int lane = tid & 31;
    const int g    = lane >> 2;
    const int tg   = lane & 3;

    const float* imgbase = image   + (size_t)ma * (AA * RBF);
    const float* vbase   = vectors + (size_t)ma * (AA * 3);
    const float* f0base  = feat0   + (size_t)m  * (AA * FF);
    const float* f1t0 = g_f1t + (size_t)(m * 3 + 0) * (AA * FF);
    const float* f1t1 = g_f1t + (size_t)(m * 3 + 1) * (AA * FF);
    const float* f1t2 = g_f1t + (size_t)(m * 3 + 2) * (AA * FF);

    // this half's 128 neighbor vectors (padded to 4)
    for (int u = tid; u < 384; u += 256)
        s_v[(u / 3) * 4 + (u % 3)] = vbase[half * 384 + u];

    // ---- stage image hi/lo tf32 into pitch-68 rows (coalesced LDG) ----
#pragma unroll
    for (int j = 0; j < 8; j++) {
        const int idx = j * 256 + tid;   // float4 index over [128b][16kq]
        const int b   = idx >> 4;
        const int kq  = idx & 15;
        float4 v = __ldg((const float4*)(imgbase +
                    (size_t)(half * 128 + b) * RBF) + kq);
        float4 hi, lo;
        hi.x = tf32_rna(v.x); lo.x = tf32_rna(v.x - hi.x);
        hi.y = tf32_rna(v.y); lo.y = tf32_rna(v.y - hi.y);
        hi.z = tf32_rna(v.z); lo.z = tf32_rna(v.z - hi.z);
        hi.w = tf32_rna(v.w); lo.w = tf32_rna(v.w - hi.w);
        *(float4*)(s_Ih + b * PITCH_I + kq * 4) = hi;
        *(float4*)(s_Il + b * PITCH_I + kq * 4) = lo;
    }
    __syncthreads();

    // ---- GEMM: 8 k-steps x 16 n-tiles x 3 mma ----
    float acc[16][4];
#pragma unroll
    for (int nt = 0; nt < 16; nt++)
#pragma unroll
        for (int j = 0; j < 4; j++) acc[nt][j] = 0.f;

#pragma unroll
    for (int kt = 0; kt < 8; kt++) {
        const uint4 ah = *(const uint4*)(g_WfH + ((w * 8 + kt) * 32 + lane) * 4);
        const uint4 al = *(const uint4*)(g_WfL + ((w * 8 + kt) * 32 + lane) * 4);
        const int ko = kt * 8 + tg;
#pragma unroll
        for (int nt = 0; nt < 16; nt++) {
            const int boff = (nt * 8 + g) * PITCH_I + ko;
            const uint32_t bh0 = __float_as_uint(s_Ih[boff]);
            const uint32_t bh1 = __float_as_uint(s_Ih[boff + 4]);
            const uint32_t bl0 = __float_as_uint(s_Il[boff]);
            const uint32_t bl1 = __float_as_uint(s_Il[boff + 4]);
            mma_tf32(acc[nt], ah, bh0, bh1);   // Wh * Ih
            mma_tf32(acc[nt], ah, bl0, bl1);   // Wh * Il
            mma_tf32(acc[nt], al, bh0, bh1);   // Wl * Ih
        }
    }
    __syncthreads();   // all smem reads done; overlay R

    // ---- write R[c][b] (pitch 129) from D frags ----
    {
        const int c0 = 16 * w + g;
#pragma unroll
        for (int nt = 0; nt < 16; nt++) {
            const int b0 = nt * 8 + 2 * tg;
            s_R[c0 * PITCH_R + b0]           = acc[nt][0];
            s_R[c0 * PITCH_R + b0 + 1]       = acc[nt][1];
            s_R[(c0 + 8) * PITCH_R + b0]     = acc[nt][2];
            s_R[(c0 + 8) * PITCH_R + b0 + 1] = acc[nt][3];
        }
    }
    __syncthreads();

    // ---- phase B contraction: warp w owns 16 b-rows; lane = f ----
    const float bias0 = g_bias[lane];
    const float bias1 = g_bias[32 + lane];
    const float bias2 = g_bias[64 + lane];
    const float bias3 = g_bias[96 + lane];

    float a[11];
#pragma unroll
    for (int j = 0; j < 11; j++) a[j] = 0.f;

#pragma unroll 4
    for (int i = 0; i < 16; i++) {
        const int bl = w * 16 + i;            // local b row
        const int b  = half * 128 + bl;       // global neighbor
        const float p0 = __ldg(f0base + b * FF + lane);
        const float q0 = __ldg(f1t0 + b * FF + lane);
        const float q1 = __ldg(f1t1 + b * FF + lane);
        const float q2 = __ldg(f1t2 + b * FF + lane);
        const float vx = s_v[bl * 4], vy = s_v[bl * 4 + 1], vz = s_v[bl * 4 + 2];
        const float r00 = s_R[lane * PITCH_R + bl] + bias0;
        const float r01 = s_R[(32 + lane) * PITCH_R + bl] + bias1;
        const float r10 = s_R[(64 + lane) * PITCH_R + bl] + bias2;
        const float r11 = s_R[(96 + lane) * PITCH_R + bl] + bias3;
        const float n2 = vx * vx + vy * vy + vz * vz;
        const float mk = (n2 < 1e-14f) ? 0.f : 1.f;

        a[0] += r00 * p0;                        // out_0x0_0
        const float t1 = r01 * mk * p0;          // out_0x1_1
        a[1] += t1 * vx;  a[2] += t1 * vy;  a[3] += t1 * vz;
        a[4] += r10 * q0; a[5] += r10 * q1; a[6] += r10 * q2;  // out_1x0_1
        const float rm = r11 * mk;               // out_1x1_0 / _1
        a[7]  += rm * (vx * q0 + vy * q1 + vz * q2);
        a[8]  += rm * (vy * q2 - vz * q1);
        a[9]  += rm * (vz * q0 - vx * q2);
        a[10] += rm * (vx * q1 - vy * q0);
    }

    // ---- cross-warp reduction -> global partials ----
#pragma unroll
    for (int j = 0; j < 11; j++) s_red[(w * 32 + lane) * 11 + j] = a[j];
    __syncthreads();

    float* part = g_part + (size_t)(half * (MM * AA) + ma) * 352;
    for (int idx = tid; idx < 352; idx += 256) {
        const int f = idx / 11, col = idx % 11;
        float s = 0.f;
#pragma unroll
        for (int g2 = 0; g2 < 8; g2++)
            s += s_red[(g2 * 32 + f) * 11 + col];
        part[idx] = s;
    }
}

// ---------------------------------------------------------------------------
// Finish: combine halves, self-interaction, equivariant activation.
// ---------------------------------------------------------------------------
__global__ void __launch_bounds__(64) finish_kernel(
    const float* __restrict__ w_si0,
    const float* __restrict__ w_si1,
    const float* __restrict__ b_act0,
    const float* __restrict__ b_act1,
    float* __restrict__ out)
{
    __shared__ float s_cat[352];
    const int ma  = blockIdx.x;
    const int tid = threadIdx.x;

    const float* p0 = g_part + (size_t)ma * 352;
    const float* p1 = g_part + (size_t)(MM * AA + ma) * 352;
    for (int idx = tid; idx < 352; idx += 64)
        s_cat[idx] = p0[idx] + p1[idx];
    __syncthreads();

    if (tid < 32) {
        const int g = tid;
        const float* w0p = w_si0 + g * (2 * FF);
        const float* w1p = w_si1 + g * (3 * FF);
        float si0 = 0.f, sx = 0.f, sy = 0.f, sz = 0.f;
#pragma unroll 8
        for (int f2 = 0; f2 < 32; f2++) {
            const float* c = s_cat + f2 * 11;
            si0 += w0p[f2] * c[0] + w0p[32 + f2] * c[7];
            const float wa = w1p[f2], wb = w1p[32 + f2], wc = w1p[64 + f2];
            sx += wa * c[1] + wb * c[4] + wc * c[8];
            sy += wa * c[2] + wb * c[5] + wc * c[9];
            sz += wa * c[3] + wb * c[6] + wc * c[10];
        }
        const float o0v = sspf(si0 + b_act0[g]);
        const float nn  = sx * sx + sy * sy + sz * sz;
        const float n1  = sqrtf(fmaxf(nn, 1e-7f));
        const float a1v = sspf(n1 + b_act1[g]);
        const float sc  = a1v / n1;

        out[(size_t)ma * SI + g] = o0v;                      // o0: (M,A,SI,1)
        float* o1 = out + (size_t)MM * AA * SI + ((size_t)ma * SI + g) * 3;
        o1[0] = sx * sc;
        o1[1] = sy * sc;
        o1[2] = sz * sc;
    }
}

// ---------------------------------------------------------------------------
extern "C" void kernel_launch(void* const* d_in, const int* in_sizes, int n_in,
                              void* d_out, int out_size)
{
    (void)in_sizes; (void)n_in; (void)out_size;

    const float* image   = (const float*)d_in[0];
    const float* vectors = (const float*)d_in[1];
    const float* feat0   = (const float*)d_in[2];
    const float* feat1   = (const float*)d_in[3];

    Wptrs wp;
    for (int filt = 0; filt < 4; filt++) {
        wp.w1[filt] = (const float*)d_in[4 + filt * 4 + 0];
        wp.b1[filt] = (const float*)d_in[4 + filt * 4 + 1];
        wp.w2[filt] = (const float*)d_in[4 + filt * 4 + 2];
        wp.b2[filt] = (const float*)d_in[4 + filt * 4 + 3];
    }
    const float* w_si0  = (const float*)d_in[20];
    const float* w_si1  = (const float*)d_in[21];
    const float* b_act0 = (const float*)d_in[22];
    const float* b_act1 = (const float*)d_in[23];

    const int smem_bytes = SMEM_FLOATS * (int)sizeof(float);
    cudaFuncSetAttribute(conv_kernel,
                         cudaFuncAttributeMaxDynamicSharedMemorySize,
                         smem_bytes);

    const int prep_total = N_F1Q + N_WFR + CC;
    prep_all<<<(prep_total + 255) / 256, 256>>>(wp, feat1);
    conv_kernel<<<MM * AA * 2, 256, smem_bytes>>>(image, vectors, feat0);
    finish_kernel<<<MM * AA, 64>>>(w_si0, w_si1, b_act0, b_act1,
                                   (float*)d_out);
}